// round 14
// baseline (speedup 1.0000x reference)
#include <cuda_runtime.h>
#include <cuda_fp16.h>
#include <math.h>
#include <stdint.h>

#define B_   2
#define S_   2048
#define HID_ 2048
#define NH_  16
#define HD_  128
#define ROT_ 64
#define M_   (B_*S_)

// quantization scales (per-tensor, fixed with clamping headroom)
#define S_H8   (7.0f/127.0f)                 // H ~ N(0,1)
#define S_WL   (6.103515625e-05f/127.0f)     // 2^-14/127  (half-ulp of fp16 at Wmax)
#define S_Q8   (0.7f/127.0f)                 // Q pre-scaled by 1/sqrt(128), sigma~0.088
#define S_KL   (1.953125e-03f/127.0f)        // 2^-9/127   (half-ulp of fp16 at Kmax)
#define SHW_   (S_H8*S_WL)
#define SQK_   (S_Q8*S_KL)

// ---------------- scratch (no allocations allowed) ----------------
__device__ __align__(128) __half  g_Hh [(size_t)M_*HID_];
__device__ __align__(128) int8_t  g_H8 [(size_t)M_*HID_];
__device__ __align__(128) __half  g_Whi[3][(size_t)HID_*HID_];
__device__ __align__(128) int8_t  g_Wl8[3][(size_t)HID_*HID_];
__device__ __align__(128) __half  g_Qh [(size_t)B_*NH_*S_*HD_];
__device__ __align__(128) int8_t  g_Q8 [(size_t)B_*NH_*S_*HD_];
__device__ __align__(128) __half  g_Khi[(size_t)B_*NH_*S_*HD_];
__device__ __align__(128) int8_t  g_Kl8[(size_t)B_*NH_*S_*HD_];
__device__ __align__(128) __half  g_Vhi[(size_t)B_*NH_*S_*HD_];
__device__ __align__(128) __half  g_Vlo[(size_t)B_*NH_*S_*HD_];
__device__ __align__(128) float2  g_rope[S_*ROT_/2];

// ================= helpers =================
__device__ __forceinline__ uint32_t smem_u32(const void* p) {
    return (uint32_t)__cvta_generic_to_shared(p);
}
__device__ __forceinline__ void split_f16(float x, __half& hi, __half& lo) {
    hi = __float2half_rn(x);
    lo = __float2half_rn(x - __half2float(hi));
}
__device__ __forceinline__ uint32_t pack_h2(float x, float y) {
    __half2 t = __floats2half2_rn(x, y);
    return *(uint32_t*)&t;
}
__device__ __forceinline__ int8_t q8(float x, float inv_s) {
    float v = rintf(x*inv_s);
    v = fminf(fmaxf(v, -127.f), 127.f);
    return (int8_t)(int)v;
}
__device__ __forceinline__ void ldmx4(uint32_t& r0, uint32_t& r1, uint32_t& r2, uint32_t& r3, uint32_t a) {
    asm volatile("ldmatrix.sync.aligned.m8n8.x4.shared.b16 {%0,%1,%2,%3},[%4];"
                 : "=r"(r0), "=r"(r1), "=r"(r2), "=r"(r3) : "r"(a));
}
__device__ __forceinline__ void ldmx4t(uint32_t& r0, uint32_t& r1, uint32_t& r2, uint32_t& r3, uint32_t a) {
    asm volatile("ldmatrix.sync.aligned.m8n8.x4.trans.shared.b16 {%0,%1,%2,%3},[%4];"
                 : "=r"(r0), "=r"(r1), "=r"(r2), "=r"(r3) : "r"(a));
}
__device__ __forceinline__ void ldmx2(uint32_t& r0, uint32_t& r1, uint32_t a) {
    asm volatile("ldmatrix.sync.aligned.m8n8.x2.shared.b16 {%0,%1},[%2];"
                 : "=r"(r0), "=r"(r1) : "r"(a));
}
__device__ __forceinline__ void mma_fp16(float* c, const uint32_t* a, const uint32_t* b) {
    asm volatile(
        "mma.sync.aligned.m16n8k16.row.col.f32.f16.f16.f32 "
        "{%0,%1,%2,%3},{%4,%5,%6,%7},{%8,%9},{%0,%1,%2,%3};"
        : "+f"(c[0]), "+f"(c[1]), "+f"(c[2]), "+f"(c[3])
        : "r"(a[0]), "r"(a[1]), "r"(a[2]), "r"(a[3]), "r"(b[0]), "r"(b[1]));
}
__device__ __forceinline__ void mma_s8(int* c, const uint32_t* a, uint32_t b0, uint32_t b1) {
    asm volatile(
        "mma.sync.aligned.m16n8k32.row.col.s32.s8.s8.s32 "
        "{%0,%1,%2,%3},{%4,%5,%6,%7},{%8,%9},{%0,%1,%2,%3};"
        : "+r"(c[0]), "+r"(c[1]), "+r"(c[2]), "+r"(c[3])
        : "r"(a[0]), "r"(a[1]), "r"(a[2]), "r"(a[3]), "r"(b0), "r"(b1));
}
__device__ __forceinline__ void cpasync16(uint32_t dst, const void* src) {
    asm volatile("cp.async.cg.shared.global [%0], [%1], 16;" :: "r"(dst), "l"(src));
}
__device__ __forceinline__ void cp_commit() { asm volatile("cp.async.commit_group;" ::: "memory"); }
template<int N> __device__ __forceinline__ void cp_wait() {
    asm volatile("cp.async.wait_group %0;" :: "n"(N) : "memory");
}

// ================= RoPE table init =================
__global__ void rope_init_kernel() {
    int idx = blockIdx.x * 256 + threadIdx.x;
    if (idx < S_*ROT_/2) {
        int s = idx >> 5;
        int i = idx & 31;
        float inv = powf(10000.0f, -(float)(2*i) / (float)ROT_);
        float ang = (float)s * inv;
        float sn, cs; sincosf(ang, &sn, &cs);
        g_rope[idx] = make_float2(sn, cs);
    }
}

// ================= fp32 -> fp16 (+int8) planes =================
__global__ __launch_bounds__(256)
void convert_kernel(const float* __restrict__ H,
                    const float* __restrict__ Wq,
                    const float* __restrict__ Wk,
                    const float* __restrict__ Wv)
{
    const int t = blockIdx.y;
    const float* src = (t==0) ? H : (t==1) ? Wq : (t==2) ? Wk : Wv;
    const size_t n4 = ((t==0) ? (size_t)M_*HID_ : (size_t)HID_*HID_) / 4;
    size_t i = (size_t)blockIdx.x * 256 + threadIdx.x;
    if (i >= n4) return;
    float4 v = *(const float4*)(src + i*4);
    float xs[4] = {v.x, v.y, v.z, v.w};
    if (t == 0) {
        uint2 p = make_uint2(pack_h2(v.x, v.y), pack_h2(v.z, v.w));
        *(uint2*)(g_Hh + i*4) = p;
        char4 c;
        c.x = q8(xs[0], 1.0f/S_H8); c.y = q8(xs[1], 1.0f/S_H8);
        c.z = q8(xs[2], 1.0f/S_H8); c.w = q8(xs[3], 1.0f/S_H8);
        *(char4*)(g_H8 + i*4) = c;
    } else {
        __half h[4]; float lo[4];
        #pragma unroll
        for (int e=0;e<4;e++) {
            h[e] = __float2half_rn(xs[e]);
            lo[e] = xs[e] - __half2float(h[e]);
        }
        uint2 ph = make_uint2(pack_h2(__half2float(h[0]),__half2float(h[1])),
                              pack_h2(__half2float(h[2]),__half2float(h[3])));
        *(uint2*)(g_Whi[t-1] + i*4) = ph;
        char4 c;
        c.x = q8(lo[0], 1.0f/S_WL); c.y = q8(lo[1], 1.0f/S_WL);
        c.z = q8(lo[2], 1.0f/S_WL); c.w = q8(lo[3], 1.0f/S_WL);
        *(char4*)(g_Wl8[t-1] + i*4) = c;
    }
}

// ================= QKV projection: fp16 + int8-correction GEMM =================
#define BM 128
#define BN 64
#define BK 32
#define NKS (HID_/BK)          // 64
#define QASTR 40               // fp16 row stride (80 B)
#define ASTR8 48               // int8 row stride (48 B)

__global__ __launch_bounds__(256)
void qkv_kernel(const float* __restrict__ bq,
                const float* __restrict__ bk,
                const float* __restrict__ bv)
{
    __shared__ __align__(16) __half sA [2][BM*QASTR];   // 10240 B each
    __shared__ __align__(16) __half sBh[2][BN*QASTR];   // 5120 B each
    __shared__ __align__(16) int8_t sA8[2][BM*ASTR8];   // 6144 B each
    __shared__ __align__(16) int8_t sB8[2][BN*ASTR8];   // 3072 B each

    const int z  = blockIdx.z;
    const float* bias = (z==0) ? bq : (z==1) ? bk : bv;
    const __half* Whi_ = g_Whi[z];
    const int8_t* Wl8_ = g_Wl8[z];

    const int tid  = threadIdx.x;
    const int lane = tid & 31;
    const int wid  = tid >> 5;
    const int wm   = wid & 3;
    const int wn   = wid >> 2;
    const int m0   = blockIdx.y * BM;
    const int n0   = blockIdx.x * BN;

    const uint32_t aB[2]  = { smem_u32(&sA [0][0]), smem_u32(&sA [1][0]) };
    const uint32_t bhB[2] = { smem_u32(&sBh[0][0]), smem_u32(&sBh[1][0]) };
    const uint32_t a8B[2] = { smem_u32(&sA8[0][0]), smem_u32(&sA8[1][0]) };
    const uint32_t b8B[2] = { smem_u32(&sB8[0][0]), smem_u32(&sB8[1][0]) };

    float acc[2][4][4];
    int   aci[2][4][4];
    #pragma unroll
    for (int i=0;i<2;i++)
        #pragma unroll
        for (int j=0;j<4;j++)
            #pragma unroll
            for (int e=0;e<4;e++) { acc[i][j][e]=0.f; aci[i][j][e]=0; }

    const int a_row = lane & 15;
    const int a_col = ((lane >> 4) & 1) * 8;   // b16 units
    const int b_row = lane & 7;
    const int b_col = ((lane >> 3) & 1) * 8;   // b16 units

    auto load_stage = [&](int st, int k0) {
        #pragma unroll
        for (int it = 0; it < 2; it++) {          // A fp16: 128 rows x 4 chunks
            int i = tid + it*256;
            int r = i >> 2, c = i & 3;
            cpasync16(aB[st] + r*80 + c*16, g_Hh + (size_t)(m0 + r)*HID_ + k0 + c*8);
        }
        {                                          // B fp16 hi: 64 rows x 4 chunks
            int r = tid >> 2, c = tid & 3;
            cpasync16(bhB[st] + r*80 + c*16, Whi_ + (size_t)(n0 + r)*HID_ + k0 + c*8);
        }
        {                                          // A int8: 128 rows x 2 chunks
            int r = tid >> 1, c = tid & 1;
            cpasync16(a8B[st] + r*ASTR8 + c*16, g_H8 + (size_t)(m0 + r)*HID_ + k0 + c*16);
        }
        if (tid < 128) {                           // B int8 lo: 64 rows x 2 chunks
            int r = tid >> 1, c = tid & 1;
            cpasync16(b8B[st] + r*ASTR8 + c*16, Wl8_ + (size_t)(n0 + r)*HID_ + k0 + c*16);
        }
        cp_commit();
    };

    load_stage(0, 0);

    for (int ks = 0; ks < NKS; ks++) {
        const int cur = ks & 1;
        if (ks + 1 < NKS) {
            load_stage(cur ^ 1, (ks+1)*BK);
            cp_wait<1>();
        } else {
            cp_wait<0>();
        }
        __syncthreads();

        // ---- fp16 hi-term: 2 k16 chunks ----
        #pragma unroll
        for (int k16 = 0; k16 < BK; k16 += 16) {
            uint32_t a[2][4], bh[4][2];
            #pragma unroll
            for (int mi=0; mi<2; mi++) {
                int row = wm*32 + mi*16 + a_row;
                ldmx4(a[mi][0],a[mi][1],a[mi][2],a[mi][3],
                      aB[cur] + (row*QASTR + k16 + a_col)*2);
            }
            #pragma unroll
            for (int nj=0; nj<4; nj++) {
                int row = wn*32 + nj*8 + b_row;
                ldmx2(bh[nj][0], bh[nj][1], bhB[cur] + (row*QASTR + k16 + b_col)*2);
            }
            #pragma unroll
            for (int mi=0; mi<2; mi++)
                #pragma unroll
                for (int nj=0; nj<4; nj++)
                    mma_fp16(acc[mi][nj], a[mi], bh[nj]);
        }

        // ---- int8 lo-correction: 1 k32 chunk ----
        {
            uint32_t a8[2][4], b8[4][2];
            #pragma unroll
            for (int mi=0; mi<2; mi++) {
                int row = wm*32 + mi*16 + a_row;
                ldmx4(a8[mi][0],a8[mi][1],a8[mi][2],a8[mi][3],
                      a8B[cur] + row*ASTR8 + a_col*2);
            }
            #pragma unroll
            for (int nj=0; nj<4; nj++) {
                int row = wn*32 + nj*8 + b_row;
                ldmx2(b8[nj][0], b8[nj][1], b8B[cur] + row*ASTR8 + b_col*2);
            }
            #pragma unroll
            for (int mi=0; mi<2; mi++)
                #pragma unroll
                for (int nj=0; nj<4; nj++)
                    mma_s8(aci[mi][nj], a8[mi], b8[nj][0], b8[nj][1]);
        }
        __syncthreads();
    }

    // ---- epilogue: combine + bias + RoPE -> planes [b][h][s][d] ----
    const float qscale = 0.08838834764831845f;
    #pragma unroll
    for (int mi=0; mi<2; mi++) {
        #pragma unroll
        for (int nj=0; nj<4; nj++) {
            const int n  = n0 + wn*32 + nj*8 + (lane&3)*2;
            const int hh = n >> 7;
            const int d  = n & 127;
            const float bx = __ldg(&bias[n]), by = __ldg(&bias[n+1]);
            #pragma unroll
            for (int hf=0; hf<2; hf++) {
                const int m  = m0 + wm*32 + mi*16 + (lane>>2) + hf*8;
                const int bb = m >> 11;
                const int s  = m & 2047;
                float x = acc[mi][nj][hf*2+0] + SHW_*(float)aci[mi][nj][hf*2+0] + bx;
                float y = acc[mi][nj][hf*2+1] + SHW_*(float)aci[mi][nj][hf*2+1] + by;
                if (z < 2 && d < ROT_) {
                    float2 sc = g_rope[s*(ROT_/2) + (d>>1)];
                    float nx = x*sc.y - y*sc.x;
                    float ny = y*sc.y + x*sc.x;
                    x = nx; y = ny;
                }
                const size_t o = (((size_t)bb*NH_ + hh)*S_ + s)*(size_t)HD_ + d;
                if (z == 0) {
                    float xs = x*qscale, ys = y*qscale;
                    *(uint32_t*)(g_Qh + o) = pack_h2(xs, ys);
                    char2 c; c.x = q8(xs, 1.0f/S_Q8); c.y = q8(ys, 1.0f/S_Q8);
                    *(char2*)(g_Q8 + o) = c;
                } else if (z == 1) {
                    __half xh = __float2half_rn(x), yh = __float2half_rn(y);
                    *(uint32_t*)(g_Khi + o) = pack_h2(__half2float(xh), __half2float(yh));
                    char2 c;
                    c.x = q8(x - __half2float(xh), 1.0f/S_KL);
                    c.y = q8(y - __half2float(yh), 1.0f/S_KL);
                    *(char2*)(g_Kl8 + o) = c;
                } else {
                    __half xh,xl,yh,yl;
                    split_f16(x, xh, xl);
                    split_f16(y, yh, yl);
                    *(uint32_t*)(g_Vhi + o) = pack_h2(__half2float(xh), __half2float(yh));
                    *(uint32_t*)(g_Vlo + o) = pack_h2(__half2float(xl), __half2float(yl));
                }
            }
        }
    }
}

// ================= causal flash attention (fp16 + int8 S-correction) =================
#define AQ  128
#define AK  64
#define KSTR 136      // fp16 row stride in halves (272 B)
#define KSTR8 144     // int8 row stride in bytes

// byte offsets in dynamic smem
#define OFF_Q    0
#define OFF_Q8   (AQ*KSTR*2)                       // 34816
#define OFF_STG  (OFF_Q8 + AQ*KSTR8)               // 53248
#define STG_KL8  (AK*KSTR*2)                       // 17408 (after Kh)
#define STG_VH   (STG_KL8 + AK*KSTR8)              // 26624
#define STG_VL   (STG_VH + AK*KSTR*2)              // 44032
#define STG_SZ   (STG_VL + AK*KSTR*2)              // 61440
#define OFF_MS   (OFF_STG + 2*STG_SZ)              // 176128
#define AT_SMEM_BYTES (OFF_MS + 2*64*4)            // 176640

__global__ __launch_bounds__(256)
void attn_kernel(const float* __restrict__ amask, float* __restrict__ out)
{
    extern __shared__ __align__(16) char smraw[];
    const uint32_t smb = smem_u32(smraw);

    const int qt = (gridDim.x - 1) - blockIdx.x;
    const int h  = blockIdx.y, b = blockIdx.z;
    const size_t hoff = ((size_t)b*NH_ + h)*S_*HD_;
    const __half* Qg   = g_Qh  + hoff;
    const int8_t* Q8g  = g_Q8  + hoff;
    const __half* Khg  = g_Khi + hoff;
    const int8_t* Kl8g = g_Kl8 + hoff;
    const __half* Vhg  = g_Vhi + hoff;
    const __half* Vlg  = g_Vlo + hoff;

    const int tid  = threadIdx.x;
    const int lane = tid & 31;
    const int w    = tid >> 5;
    const int qbase = qt*AQ + w*16;

    auto load_kv = [&](int kt, int st) {
        const uint32_t sb = smb + OFF_STG + st*STG_SZ;
        #pragma unroll
        for (int it = 0; it < 4; it++) {
            int idx = tid + it*256;
            int r = idx >> 4;
            int c = (idx & 15) * 8;                // halves
            const size_t so = (size_t)(kt*AK + r)*HD_ + c;
            cpasync16(sb + (r*KSTR + c)*2,          Khg + so);
            cpasync16(sb + STG_VH + (r*KSTR + c)*2, Vhg + so);
            cpasync16(sb + STG_VL + (r*KSTR + c)*2, Vlg + so);
        }
        #pragma unroll
        for (int it = 0; it < 2; it++) {           // Kl8: 64 rows x 8 chunks
            int idx = tid + it*256;
            int r = idx >> 3;
            int c = (idx & 7) * 16;                // bytes
            cpasync16(sb + STG_KL8 + r*KSTR8 + c, Kl8g + (size_t)(kt*AK + r)*HD_ + c);
        }
        if (tid < 16)
            cpasync16(smb + OFF_MS + st*256 + tid*16,
                      amask + (size_t)b*S_ + kt*AK + tid*4);
    };

    // ---- prologue: Q fp16 + Q int8 + stage 0 ----
    #pragma unroll
    for (int it = 0; it < 8; it++) {
        int idx = tid + it*256;
        int r = idx >> 4;
        int c = (idx & 15) * 8;
        cpasync16(smb + OFF_Q + (r*KSTR + c)*2, Qg + (size_t)(qt*AQ + r)*HD_ + c);
    }
    #pragma unroll
    for (int it = 0; it < 4; it++) {
        int idx = tid + it*256;
        int r = idx >> 3;
        int c = (idx & 7) * 16;
        cpasync16(smb + OFF_Q8 + r*KSTR8 + c, Q8g + (size_t)(qt*AQ + r)*HD_ + c);
    }
    load_kv(0, 0);
    cp_commit();

    float o[16][4];
    #pragma unroll
    for (int nt=0; nt<16; nt++)
        #pragma unroll
        for (int e=0;e<4;e++) o[nt][e]=0.f;

    float m0 = -INFINITY, m1 = -INFINITY, l0 = 0.f, l1 = 0.f;

    const int qa_row = lane & 15;
    const int qa_col = (lane >> 4) * 8;            // b16 units
    const int kb_key = (lane & 7) + ((lane >> 4) << 3);
    const int kb_col = ((lane >> 3) & 1) * 8;
    const int vb_key = (lane & 7) + (((lane >> 3) & 1) << 3);
    const int vb_col = (lane >> 4) * 8;

    cp_wait<0>();
    __syncthreads();
    // hoist Q fragments (kt-invariant): fp16 8 chunks + int8 4 chunks
    uint32_t qf[8][4];
    #pragma unroll
    for (int ks = 0; ks < 8; ks++)
        ldmx4(qf[ks][0],qf[ks][1],qf[ks][2],qf[ks][3],
              smb + OFF_Q + ((w*16+qa_row)*KSTR + ks*16 + qa_col)*2);
    uint32_t qf8[4][4];
    #pragma unroll
    for (int kc = 0; kc < 4; kc++)
        ldmx4(qf8[kc][0],qf8[kc][1],qf8[kc][2],qf8[kc][3],
              smb + OFF_Q8 + (w*16+qa_row)*KSTR8 + (kc*16 + qa_col)*2);

    const int ktmax = 2*qt + 1;
    for (int kt = 0; kt <= ktmax; kt++) {
        const int cur = kt & 1;
        if (kt > 0) { cp_wait<0>(); __syncthreads(); }
        if (kt + 1 <= ktmax) { load_kv(kt+1, cur ^ 1); cp_commit(); }

        const uint32_t ksb = smb + OFF_STG + cur*STG_SZ;
        const float* ms = (const float*)(smraw + OFF_MS + cur*256);

        // ---- S = Q·Kh (fp16) + SQK·(Q8·Kl8) (int8) ----
        float s[8][4];
        #pragma unroll
        for (int ntp = 0; ntp < 4; ntp++) {
            const int n0 = ntp*16;
            float c0[4] = {0.f,0.f,0.f,0.f}, c1[4] = {0.f,0.f,0.f,0.f};
            int   i0[4] = {0,0,0,0},         i1[4] = {0,0,0,0};
            #pragma unroll
            for (int ks = 0; ks < 8; ks++) {
                const int d0 = ks*16;
                uint32_t bh[4];
                ldmx4(bh[0],bh[1],bh[2],bh[3], ksb + ((n0+kb_key)*KSTR + d0 + kb_col)*2);
                mma_fp16(c0, qf[ks], &bh[0]);
                mma_fp16(c1, qf[ks], &bh[2]);
            }
            #pragma unroll
            for (int kc = 0; kc < 4; kc++) {
                uint32_t bl[4];
                ldmx4(bl[0],bl[1],bl[2],bl[3],
                      ksb + STG_KL8 + (n0 + (lane&15))*KSTR8 + (kc*16 + qa_col)*2);
                mma_s8(i0, qf8[kc], bl[0], bl[2]);
                mma_s8(i1, qf8[kc], bl[1], bl[3]);
            }
            #pragma unroll
            for (int e=0;e<4;e++) {
                s[ntp*2  ][e] = c0[e] + SQK_*(float)i0[e];
                s[ntp*2+1][e] = c1[e] + SQK_*(float)i1[e];
            }
        }

        // ---- causal + amask ----
        const int qi0 = qbase + (lane>>2);
        const int qi1 = qi0 + 8;
        #pragma unroll
        for (int nt=0; nt<8; nt++) {
            const int kc = kt*AK + nt*8 + (lane&3)*2;
            const float am0 = ms[nt*8 + (lane&3)*2];
            const float am1 = ms[nt*8 + (lane&3)*2 + 1];
            s[nt][0] = ((kc   <= qi0) ? s[nt][0] : -10000.f) + am0;
            s[nt][1] = ((kc+1 <= qi0) ? s[nt][1] : -10000.f) + am1;
            s[nt][2] = ((kc   <= qi1) ? s[nt][2] : -10000.f) + am0;
            s[nt][3] = ((kc+1 <= qi1) ? s[nt][3] : -10000.f) + am1;
        }

        // ---- online softmax ----
        float mx0 = -INFINITY, mx1 = -INFINITY;
        #pragma unroll
        for (int nt=0; nt<8; nt++) {
            mx0 = fmaxf(mx0, fmaxf(s[nt][0], s[nt][1]));
            mx1 = fmaxf(mx1, fmaxf(s[nt][2], s[nt][3]));
        }
        mx0 = fmaxf(mx0, __shfl_xor_sync(0xffffffffu, mx0, 1));
        mx0 = fmaxf(mx0, __shfl_xor_sync(0xffffffffu, mx0, 2));
        mx1 = fmaxf(mx1, __shfl_xor_sync(0xffffffffu, mx1, 1));
        mx1 = fmaxf(mx1, __shfl_xor_sync(0xffffffffu, mx1, 2));
        const float mn0 = fmaxf(m0, mx0), mn1 = fmaxf(m1, mx1);
        const float al0 = __expf(m0 - mn0), al1 = __expf(m1 - mn1);
        m0 = mn0; m1 = mn1;

        float sum0 = 0.f, sum1 = 0.f;
        #pragma unroll
        for (int nt=0; nt<8; nt++) {
            s[nt][0] = __expf(s[nt][0] - mn0);
            s[nt][1] = __expf(s[nt][1] - mn0);
            s[nt][2] = __expf(s[nt][2] - mn1);
            s[nt][3] = __expf(s[nt][3] - mn1);
            sum0 += s[nt][0] + s[nt][1];
            sum1 += s[nt][2] + s[nt][3];
        }
        sum0 += __shfl_xor_sync(0xffffffffu, sum0, 1);
        sum0 += __shfl_xor_sync(0xffffffffu, sum0, 2);
        sum1 += __shfl_xor_sync(0xffffffffu, sum1, 1);
        sum1 += __shfl_xor_sync(0xffffffffu, sum1, 2);
        l0 = l0*al0 + sum0;
        l1 = l1*al1 + sum1;

        #pragma unroll
        for (int nt=0; nt<16; nt++) {
            o[nt][0] *= al0; o[nt][1] *= al0;
            o[nt][2] *= al1; o[nt][3] *= al1;
        }

        // ---- O += P V (P fp16, V hi+lo fp16) ----
        #pragma unroll
        for (int ks = 0; ks < 4; ks++) {
            const int t0 = 2*ks, t1 = 2*ks+1;
            uint32_t pa[4];
            pa[0] = pack_h2(s[t0][0], s[t0][1]);
            pa[1] = pack_h2(s[t0][2], s[t0][3]);
            pa[2] = pack_h2(s[t1][0], s[t1][1]);
            pa[3] = pack_h2(s[t1][2], s[t1][3]);
            const int k0 = ks*16;
            #pragma unroll
            for (int ntp = 0; ntp < 8; ntp++) {
                const int n0 = ntp*16;
                uint32_t vh[4], vl[4];
                ldmx4t(vh[0],vh[1],vh[2],vh[3], ksb + STG_VH + ((k0+vb_key)*KSTR + n0 + vb_col)*2);
                ldmx4t(vl[0],vl[1],vl[2],vl[3], ksb + STG_VL + ((k0+vb_key)*KSTR + n0 + vb_col)*2);
                mma_fp16(o[ntp*2],   pa, &vh[0]);
                mma_fp16(o[ntp*2],   pa, &vl[0]);
                mma_fp16(o[ntp*2+1], pa, &vh[2]);
                mma_fp16(o[ntp*2+1], pa, &vl[2]);
            }
        }
    }

    // ---- normalize + write ----
    const float inv0 = 1.0f / l0;
    const float inv1 = 1.0f / l1;
    const int r0 = qbase + (lane>>2);
    const int r1 = r0 + 8;
    #pragma unroll
    for (int nt=0; nt<16; nt++) {
        const int col = h*HD_ + nt*8 + (lane&3)*2;
        float2 w0 = make_float2(o[nt][0]*inv0, o[nt][1]*inv0);
        float2 w1 = make_float2(o[nt][2]*inv1, o[nt][3]*inv1);
        *(float2*)&out[(size_t)(b*S_ + r0)*HID_ + col] = w0;
        *(float2*)&out[(size_t)(b*S_ + r1)*HID_ + col] = w1;
    }
}

// ================= launch =================
extern "C" void kernel_launch(void* const* d_in, const int* in_sizes, int n_in,
                              void* d_out, int out_size)
{
    const float* H  = (const float*)d_in[0];
    const float* am = (const float*)d_in[1];
    const float* Wq = (const float*)d_in[2];
    const float* bq = (const float*)d_in[3];
    const float* Wk = (const float*)d_in[4];
    const float* bk = (const float*)d_in[5];
    const float* Wv = (const float*)d_in[6];
    const float* bv = (const float*)d_in[7];
    float* out = (float*)d_out;

    cudaFuncSetAttribute(attn_kernel,
                         cudaFuncAttributeMaxDynamicSharedMemorySize, AT_SMEM_BYTES);

    rope_init_kernel<<<(S_*ROT_/2 + 255)/256, 256>>>();

    {
        dim3 cgrid((unsigned)(((size_t)M_*HID_/4 + 255)/256), 4);
        convert_kernel<<<cgrid, 256>>>(H, Wq, Wk, Wv);
    }

    dim3 ggrid(HID_/BN, M_/BM, 3);        // 32 x 32 x 3
    qkv_kernel<<<ggrid, 256>>>(bq, bk, bv);

    dim3 agrid(S_/AQ, NH_, B_);           // 16 x 16 x 2
    attn_kernel<<<agrid, 256, AT_SMEM_BYTES>>>(am, out);
}

// round 15
// speedup vs baseline: 4.1125x; 4.1125x over previous
#include <cuda_runtime.h>
#include <cuda_fp16.h>
#include <math.h>
#include <stdint.h>

#define B_   2
#define S_   2048
#define HID_ 2048
#define NH_  16
#define HD_  128
#define ROT_ 64
#define M_   (B_*S_)

// ---------------- scratch (no allocations allowed) ----------------
__device__ __align__(128) __half  g_Hh[(size_t)M_*HID_];
__device__ __align__(128) __half  g_Wh[3][(size_t)HID_*HID_];
__device__ __align__(128) __half  g_Qh[(size_t)B_*NH_*S_*HD_];
__device__ __align__(128) __half  g_Kh[(size_t)B_*NH_*S_*HD_];
__device__ __align__(128) __half  g_Vh[(size_t)B_*NH_*S_*HD_];
__device__ __align__(128) float2  g_rope[S_*ROT_/2];

// ================= helpers =================
__device__ __forceinline__ uint32_t smem_u32(const void* p) {
    return (uint32_t)__cvta_generic_to_shared(p);
}
__device__ __forceinline__ uint32_t pack_h2(float x, float y) {
    __half2 t = __floats2half2_rn(x, y);
    return *(uint32_t*)&t;
}
__device__ __forceinline__ void ldmx4(uint32_t& r0, uint32_t& r1, uint32_t& r2, uint32_t& r3, uint32_t a) {
    asm volatile("ldmatrix.sync.aligned.m8n8.x4.shared.b16 {%0,%1,%2,%3},[%4];"
                 : "=r"(r0), "=r"(r1), "=r"(r2), "=r"(r3) : "r"(a));
}
__device__ __forceinline__ void ldmx4t(uint32_t& r0, uint32_t& r1, uint32_t& r2, uint32_t& r3, uint32_t a) {
    asm volatile("ldmatrix.sync.aligned.m8n8.x4.trans.shared.b16 {%0,%1,%2,%3},[%4];"
                 : "=r"(r0), "=r"(r1), "=r"(r2), "=r"(r3) : "r"(a));
}
__device__ __forceinline__ void ldmx2(uint32_t& r0, uint32_t& r1, uint32_t a) {
    asm volatile("ldmatrix.sync.aligned.m8n8.x2.shared.b16 {%0,%1},[%2];"
                 : "=r"(r0), "=r"(r1) : "r"(a));
}
__device__ __forceinline__ void mma_fp16(float* c, const uint32_t* a, const uint32_t* b) {
    asm volatile(
        "mma.sync.aligned.m16n8k16.row.col.f32.f16.f16.f32 "
        "{%0,%1,%2,%3},{%4,%5,%6,%7},{%8,%9},{%0,%1,%2,%3};"
        : "+f"(c[0]), "+f"(c[1]), "+f"(c[2]), "+f"(c[3])
        : "r"(a[0]), "r"(a[1]), "r"(a[2]), "r"(a[3]), "r"(b[0]), "r"(b[1]));
}
__device__ __forceinline__ void cpasync16(uint32_t dst, const void* src) {
    asm volatile("cp.async.cg.shared.global [%0], [%1], 16;" :: "r"(dst), "l"(src));
}
__device__ __forceinline__ void cp_commit() { asm volatile("cp.async.commit_group;" ::: "memory"); }
template<int N> __device__ __forceinline__ void cp_wait() {
    asm volatile("cp.async.wait_group %0;" :: "n"(N) : "memory");
}

// ================= RoPE table init =================
__global__ void rope_init_kernel() {
    int idx = blockIdx.x * 256 + threadIdx.x;
    if (idx < S_*ROT_/2) {
        int s = idx >> 5;
        int i = idx & 31;
        float inv = powf(10000.0f, -(float)(2*i) / (float)ROT_);
        float ang = (float)s * inv;
        float sn, cs; sincosf(ang, &sn, &cs);
        g_rope[idx] = make_float2(sn, cs);
    }
}

// ================= fp32 -> fp16 planes =================
__global__ __launch_bounds__(256)
void convert_kernel(const float* __restrict__ H,
                    const float* __restrict__ Wq,
                    const float* __restrict__ Wk,
                    const float* __restrict__ Wv)
{
    const int t = blockIdx.y;
    const float* src = (t==0) ? H : (t==1) ? Wq : (t==2) ? Wk : Wv;
    __half* dst = (t==0) ? g_Hh : g_Wh[t-1];
    const size_t n4 = ((t==0) ? (size_t)M_*HID_ : (size_t)HID_*HID_) / 4;
    size_t i = (size_t)blockIdx.x * 256 + threadIdx.x;
    if (i >= n4) return;
    float4 v = *(const float4*)(src + i*4);
    uint2 p = make_uint2(pack_h2(v.x, v.y), pack_h2(v.z, v.w));
    *(uint2*)(dst + i*4) = p;
}

// ================= QKV projection: fp16 mma GEMM =================
#define BM 128
#define BN 64
#define BK 32
#define NKS (HID_/BK)          // 64
#define QASTR 40               // fp16 row stride (80 B)

__global__ __launch_bounds__(256)
void qkv_kernel(const float* __restrict__ bq,
                const float* __restrict__ bk,
                const float* __restrict__ bv)
{
    __shared__ __align__(16) __half sA[2][BM*QASTR];    // 10240 B each
    __shared__ __align__(16) __half sB[2][BN*QASTR];    //  5120 B each

    const int z  = blockIdx.z;
    const float* bias = (z==0) ? bq : (z==1) ? bk : bv;
    const __half* W_ = g_Wh[z];

    const int tid  = threadIdx.x;
    const int lane = tid & 31;
    const int wid  = tid >> 5;
    const int wm   = wid & 3;
    const int wn   = wid >> 2;
    const int m0   = blockIdx.y * BM;
    const int n0   = blockIdx.x * BN;

    const uint32_t aB[2] = { smem_u32(&sA[0][0]), smem_u32(&sA[1][0]) };
    const uint32_t bB[2] = { smem_u32(&sB[0][0]), smem_u32(&sB[1][0]) };

    float acc[2][4][4];
    #pragma unroll
    for (int i=0;i<2;i++)
        #pragma unroll
        for (int j=0;j<4;j++)
            #pragma unroll
            for (int e=0;e<4;e++) acc[i][j][e]=0.f;

    const int a_row = lane & 15;
    const int a_col = ((lane >> 4) & 1) * 8;
    const int b_row = lane & 7;
    const int b_col = ((lane >> 3) & 1) * 8;

    auto load_stage = [&](int st, int k0) {
        #pragma unroll
        for (int it = 0; it < 2; it++) {          // A: 128 rows x 4 chunks of 16B
            int i = tid + it*256;
            int r = i >> 2, c = i & 3;
            cpasync16(aB[st] + r*80 + c*16, g_Hh + (size_t)(m0 + r)*HID_ + k0 + c*8);
        }
        {                                          // B: 64 rows x 4 chunks
            int r = tid >> 2, c = tid & 3;
            cpasync16(bB[st] + r*80 + c*16, W_ + (size_t)(n0 + r)*HID_ + k0 + c*8);
        }
        cp_commit();
    };

    load_stage(0, 0);

    for (int ks = 0; ks < NKS; ks++) {
        const int cur = ks & 1;
        if (ks + 1 < NKS) {
            load_stage(cur ^ 1, (ks+1)*BK);
            cp_wait<1>();
        } else {
            cp_wait<0>();
        }
        __syncthreads();

        #pragma unroll
        for (int k16 = 0; k16 < BK; k16 += 16) {
            uint32_t a[2][4], bb[4][2];
            #pragma unroll
            for (int mi=0; mi<2; mi++) {
                int row = wm*32 + mi*16 + a_row;
                ldmx4(a[mi][0],a[mi][1],a[mi][2],a[mi][3],
                      aB[cur] + (row*QASTR + k16 + a_col)*2);
            }
            #pragma unroll
            for (int nj=0; nj<4; nj++) {
                int row = wn*32 + nj*8 + b_row;
                ldmx2(bb[nj][0], bb[nj][1], bB[cur] + (row*QASTR + k16 + b_col)*2);
            }
            #pragma unroll
            for (int mi=0; mi<2; mi++)
                #pragma unroll
                for (int nj=0; nj<4; nj++)
                    mma_fp16(acc[mi][nj], a[mi], bb[nj]);
        }
        __syncthreads();
    }

    // ---- epilogue: bias + RoPE -> fp16 planes [b][h][s][d] ----
    const float qscale = 0.08838834764831845f;     // fold 1/sqrt(HD) into Q
    __half* Out = (z==0) ? g_Qh : (z==1) ? g_Kh : g_Vh;
    #pragma unroll
    for (int mi=0; mi<2; mi++) {
        #pragma unroll
        for (int nj=0; nj<4; nj++) {
            const int n  = n0 + wn*32 + nj*8 + (lane&3)*2;
            const int hh = n >> 7;
            const int d  = n & 127;
            const float bx = __ldg(&bias[n]), by = __ldg(&bias[n+1]);
            #pragma unroll
            for (int hf=0; hf<2; hf++) {
                const int m  = m0 + wm*32 + mi*16 + (lane>>2) + hf*8;
                const int bb = m >> 11;
                const int s  = m & 2047;
                float x = acc[mi][nj][hf*2+0] + bx;
                float y = acc[mi][nj][hf*2+1] + by;
                if (z < 2 && d < ROT_) {
                    float2 sc = g_rope[s*(ROT_/2) + (d>>1)];
                    float nx = x*sc.y - y*sc.x;
                    float ny = y*sc.y + x*sc.x;
                    x = nx; y = ny;
                }
                if (z == 0) { x *= qscale; y *= qscale; }
                const size_t o = (((size_t)bb*NH_ + hh)*S_ + s)*(size_t)HD_ + d;
                *(uint32_t*)(Out + o) = pack_h2(x, y);
            }
        }
    }
}

// ================= causal flash attention (plain fp16, cp.async pipelined) =================
#define AQ  128
#define AK  64
#define KSTR 136     // fp16 row stride in halves (272 B)

#define AT_Q    (AQ*KSTR)                 // halves
#define AT_P    (AK*KSTR)                 // halves per plane
#define STG_H   (2*AT_P)                  // halves per stage (Kh, Vh)
#define OFF_S0  AT_Q
#define OFF_S1  (AT_Q + STG_H)
#define OFF_MS  (AT_Q + 2*STG_H)          // then 2*64 floats
#define AT_SMEM_BYTES (OFF_MS*2 + 2*64*4)

__global__ __launch_bounds__(256)
void attn_kernel(const float* __restrict__ amask, float* __restrict__ out)
{
    extern __shared__ __align__(16) char smraw[];
    __half* SM = (__half*)smraw;
    float*  msbase = (float*)(SM + OFF_MS);
    const uint32_t smb = smem_u32(SM);

    const int qt = (gridDim.x - 1) - blockIdx.x;   // heavy tiles first
    const int h  = blockIdx.y, b = blockIdx.z;
    const size_t hoff = ((size_t)b*NH_ + h)*S_*HD_;
    const __half* Qg = g_Qh + hoff;
    const __half* Kg = g_Kh + hoff;
    const __half* Vg = g_Vh + hoff;

    const int tid  = threadIdx.x;
    const int lane = tid & 31;
    const int w    = tid >> 5;
    const int qbase = qt*AQ + w*16;

    auto load_kv = [&](int kt, int st) {
        const uint32_t sb = smb + (st ? OFF_S1 : OFF_S0)*2;
        #pragma unroll
        for (int it = 0; it < 4; it++) {
            int idx = tid + it*256;            // 1024 chunks of 16B per plane
            int r = idx >> 4;
            int c = (idx & 15) * 8;            // halves
            const size_t so = (size_t)(kt*AK + r)*HD_ + c;
            cpasync16(sb + (r*KSTR + c)*2,          Kg + so);
            cpasync16(sb + AT_P*2 + (r*KSTR + c)*2, Vg + so);
        }
        if (tid < 16)
            cpasync16(smb + OFF_MS*2 + st*256 + tid*16,
                      amask + (size_t)b*S_ + kt*AK + tid*4);
    };

    // ---- prologue: Q + stage 0 ----
    #pragma unroll
    for (int it = 0; it < 8; it++) {
        int idx = tid + it*256;
        int r = idx >> 4;
        int c = (idx & 15) * 8;
        cpasync16(smb + (r*KSTR + c)*2, Qg + (size_t)(qt*AQ + r)*HD_ + c);
    }
    load_kv(0, 0);
    cp_commit();

    float o[16][4];
    #pragma unroll
    for (int nt=0; nt<16; nt++)
        #pragma unroll
        for (int e=0;e<4;e++) o[nt][e]=0.f;

    float m0 = -INFINITY, m1 = -INFINITY, l0 = 0.f, l1 = 0.f;

    const int qa_row = lane & 15;
    const int qa_col = (lane >> 4) * 8;
    const int kb_key = (lane & 7) + ((lane >> 4) << 3);
    const int kb_col = ((lane >> 3) & 1) * 8;
    const int vb_key = (lane & 7) + (((lane >> 3) & 1) << 3);
    const int vb_col = (lane >> 4) * 8;

    // wait prologue, hoist Q fragments (kt-invariant)
    cp_wait<0>();
    __syncthreads();
    uint32_t qf[8][4];
    #pragma unroll
    for (int ks = 0; ks < 8; ks++)
        ldmx4(qf[ks][0],qf[ks][1],qf[ks][2],qf[ks][3],
              smb + ((w*16+qa_row)*KSTR + ks*16 + qa_col)*2);

    const int ktmax = 2*qt + 1;
    for (int kt = 0; kt <= ktmax; kt++) {
        const int cur = kt & 1;
        if (kt > 0) { cp_wait<0>(); __syncthreads(); }
        if (kt + 1 <= ktmax) { load_kv(kt+1, cur ^ 1); cp_commit(); }

        const uint32_t ksb = smb + (cur ? OFF_S1 : OFF_S0)*2;
        const float* ms = msbase + cur*64;

        // ---- S = Q K^T ----
        float s[8][4];
        #pragma unroll
        for (int nt=0; nt<8; nt++)
            #pragma unroll
            for (int e=0;e<4;e++) s[nt][e]=0.f;

        #pragma unroll
        for (int ks = 0; ks < 8; ks++) {
            const int d0 = ks*16;
            #pragma unroll
            for (int ntp = 0; ntp < 4; ntp++) {
                const int n0 = ntp*16;
                uint32_t bh[4];
                ldmx4(bh[0],bh[1],bh[2],bh[3], ksb + ((n0+kb_key)*KSTR + d0 + kb_col)*2);
                mma_fp16(s[ntp*2],   qf[ks], &bh[0]);
                mma_fp16(s[ntp*2+1], qf[ks], &bh[2]);
            }
        }

        // ---- causal + amask (scale folded into Q) ----
        const int qi0 = qbase + (lane>>2);
        const int qi1 = qi0 + 8;
        #pragma unroll
        for (int nt=0; nt<8; nt++) {
            const int kc = kt*AK + nt*8 + (lane&3)*2;
            const float am0 = ms[nt*8 + (lane&3)*2];
            const float am1 = ms[nt*8 + (lane&3)*2 + 1];
            s[nt][0] = ((kc   <= qi0) ? s[nt][0] : -10000.f) + am0;
            s[nt][1] = ((kc+1 <= qi0) ? s[nt][1] : -10000.f) + am1;
            s[nt][2] = ((kc   <= qi1) ? s[nt][2] : -10000.f) + am0;
            s[nt][3] = ((kc+1 <= qi1) ? s[nt][3] : -10000.f) + am1;
        }

        // ---- online softmax ----
        float mx0 = -INFINITY, mx1 = -INFINITY;
        #pragma unroll
        for (int nt=0; nt<8; nt++) {
            mx0 = fmaxf(mx0, fmaxf(s[nt][0], s[nt][1]));
            mx1 = fmaxf(mx1, fmaxf(s[nt][2], s[nt][3]));
        }
        mx0 = fmaxf(mx0, __shfl_xor_sync(0xffffffffu, mx0, 1));
        mx0 = fmaxf(mx0, __shfl_xor_sync(0xffffffffu, mx0, 2));
        mx1 = fmaxf(mx1, __shfl_xor_sync(0xffffffffu, mx1, 1));
        mx1 = fmaxf(mx1, __shfl_xor_sync(0xffffffffu, mx1, 2));
        const float mn0 = fmaxf(m0, mx0), mn1 = fmaxf(m1, mx1);
        const float al0 = __expf(m0 - mn0), al1 = __expf(m1 - mn1);
        m0 = mn0; m1 = mn1;

        float sum0 = 0.f, sum1 = 0.f;
        #pragma unroll
        for (int nt=0; nt<8; nt++) {
            s[nt][0] = __expf(s[nt][0] - mn0);
            s[nt][1] = __expf(s[nt][1] - mn0);
            s[nt][2] = __expf(s[nt][2] - mn1);
            s[nt][3] = __expf(s[nt][3] - mn1);
            sum0 += s[nt][0] + s[nt][1];
            sum1 += s[nt][2] + s[nt][3];
        }
        sum0 += __shfl_xor_sync(0xffffffffu, sum0, 1);
        sum0 += __shfl_xor_sync(0xffffffffu, sum0, 2);
        sum1 += __shfl_xor_sync(0xffffffffu, sum1, 1);
        sum1 += __shfl_xor_sync(0xffffffffu, sum1, 2);
        l0 = l0*al0 + sum0;
        l1 = l1*al1 + sum1;

        #pragma unroll
        for (int nt=0; nt<16; nt++) {
            o[nt][0] *= al0; o[nt][1] *= al0;
            o[nt][2] *= al1; o[nt][3] *= al1;
        }

        // ---- O += P V ----
        #pragma unroll
        for (int ks = 0; ks < 4; ks++) {
            const int t0 = 2*ks, t1 = 2*ks+1;
            uint32_t pa[4];
            pa[0] = pack_h2(s[t0][0], s[t0][1]);
            pa[1] = pack_h2(s[t0][2], s[t0][3]);
            pa[2] = pack_h2(s[t1][0], s[t1][1]);
            pa[3] = pack_h2(s[t1][2], s[t1][3]);
            const int k0 = ks*16;
            #pragma unroll
            for (int ntp = 0; ntp < 8; ntp++) {
                const int n0 = ntp*16;
                uint32_t vh[4];
                ldmx4t(vh[0],vh[1],vh[2],vh[3],
                       ksb + AT_P*2 + ((k0+vb_key)*KSTR + n0 + vb_col)*2);
                mma_fp16(o[ntp*2],   pa, &vh[0]);
                mma_fp16(o[ntp*2+1], pa, &vh[2]);
            }
        }
    }

    // ---- normalize + write out[b][s][h*HD+d] ----
    const float inv0 = 1.0f / l0;
    const float inv1 = 1.0f / l1;
    const int r0 = qbase + (lane>>2);
    const int r1 = r0 + 8;
    #pragma unroll
    for (int nt=0; nt<16; nt++) {
        const int col = h*HD_ + nt*8 + (lane&3)*2;
        float2 w0 = make_float2(o[nt][0]*inv0, o[nt][1]*inv0);
        float2 w1 = make_float2(o[nt][2]*inv1, o[nt][3]*inv1);
        *(float2*)&out[(size_t)(b*S_ + r0)*HID_ + col] = w0;
        *(float2*)&out[(size_t)(b*S_ + r1)*HID_ + col] = w1;
    }
}

// ================= launch =================
extern "C" void kernel_launch(void* const* d_in, const int* in_sizes, int n_in,
                              void* d_out, int out_size)
{
    const float* H  = (const float*)d_in[0];
    const float* am = (const float*)d_in[1];
    const float* Wq = (const float*)d_in[2];
    const float* bq = (const float*)d_in[3];
    const float* Wk = (const float*)d_in[4];
    const float* bk = (const float*)d_in[5];
    const float* Wv = (const float*)d_in[6];
    const float* bv = (const float*)d_in[7];
    float* out = (float*)d_out;

    cudaFuncSetAttribute(attn_kernel,
                         cudaFuncAttributeMaxDynamicSharedMemorySize, AT_SMEM_BYTES);

    rope_init_kernel<<<(S_*ROT_/2 + 255)/256, 256>>>();

    {   // fp32 -> fp16 planes
        dim3 cgrid((unsigned)(((size_t)M_*HID_/4 + 255)/256), 4);
        convert_kernel<<<cgrid, 256>>>(H, Wq, Wk, Wv);
    }

    dim3 ggrid(HID_/BN, M_/BM, 3);        // 32 x 32 x 3
    qkv_kernel<<<ggrid, 256>>>(bq, bk, bv);

    dim3 agrid(S_/AQ, NH_, B_);           // 16 x 16 x 2
    attn_kernel<<<agrid, 256, AT_SMEM_BYTES>>>(am, out);
}

// round 16
// speedup vs baseline: 4.3429x; 1.0560x over previous
#include <cuda_runtime.h>
#include <cuda_fp16.h>
#include <math.h>
#include <stdint.h>

#define B_   2
#define S_   2048
#define HID_ 2048
#define NH_  16
#define HD_  128
#define ROT_ 64
#define M_   (B_*S_)
#define LOG2E 1.4426950408889634f

// ---------------- scratch (no allocations allowed) ----------------
__device__ __align__(128) __half  g_Hh[(size_t)M_*HID_];
__device__ __align__(128) __half  g_Wh[3][(size_t)HID_*HID_];
__device__ __align__(128) __half  g_Qh[(size_t)B_*NH_*S_*HD_];
__device__ __align__(128) __half  g_Kh[(size_t)B_*NH_*S_*HD_];
__device__ __align__(128) __half  g_Vh[(size_t)B_*NH_*S_*HD_];
__device__ __align__(128) float2  g_rope[S_*ROT_/2];

// ================= helpers =================
__device__ __forceinline__ uint32_t smem_u32(const void* p) {
    return (uint32_t)__cvta_generic_to_shared(p);
}
__device__ __forceinline__ uint32_t pack_h2(float x, float y) {
    __half2 t = __floats2half2_rn(x, y);
    return *(uint32_t*)&t;
}
__device__ __forceinline__ void ldmx4(uint32_t& r0, uint32_t& r1, uint32_t& r2, uint32_t& r3, uint32_t a) {
    asm volatile("ldmatrix.sync.aligned.m8n8.x4.shared.b16 {%0,%1,%2,%3},[%4];"
                 : "=r"(r0), "=r"(r1), "=r"(r2), "=r"(r3) : "r"(a));
}
__device__ __forceinline__ void ldmx4t(uint32_t& r0, uint32_t& r1, uint32_t& r2, uint32_t& r3, uint32_t a) {
    asm volatile("ldmatrix.sync.aligned.m8n8.x4.trans.shared.b16 {%0,%1,%2,%3},[%4];"
                 : "=r"(r0), "=r"(r1), "=r"(r2), "=r"(r3) : "r"(a));
}
__device__ __forceinline__ void mma_fp16(float* c, const uint32_t* a, const uint32_t* b) {
    asm volatile(
        "mma.sync.aligned.m16n8k16.row.col.f32.f16.f16.f32 "
        "{%0,%1,%2,%3},{%4,%5,%6,%7},{%8,%9},{%0,%1,%2,%3};"
        : "+f"(c[0]), "+f"(c[1]), "+f"(c[2]), "+f"(c[3])
        : "r"(a[0]), "r"(a[1]), "r"(a[2]), "r"(a[3]), "r"(b[0]), "r"(b[1]));
}
__device__ __forceinline__ void cpasync16(uint32_t dst, const void* src) {
    asm volatile("cp.async.cg.shared.global [%0], [%1], 16;" :: "r"(dst), "l"(src));
}
__device__ __forceinline__ void cp_commit() { asm volatile("cp.async.commit_group;" ::: "memory"); }
template<int N> __device__ __forceinline__ void cp_wait() {
    asm volatile("cp.async.wait_group %0;" :: "n"(N) : "memory");
}

// ================= RoPE table init =================
__global__ void rope_init_kernel() {
    int idx = blockIdx.x * 256 + threadIdx.x;
    if (idx < S_*ROT_/2) {
        int s = idx >> 5;
        int i = idx & 31;
        float inv = powf(10000.0f, -(float)(2*i) / (float)ROT_);
        float ang = (float)s * inv;
        float sn, cs; sincosf(ang, &sn, &cs);
        g_rope[idx] = make_float2(sn, cs);
    }
}

// ================= fp32 -> fp16 planes =================
__global__ __launch_bounds__(256)
void convert_kernel(const float* __restrict__ H,
                    const float* __restrict__ Wq,
                    const float* __restrict__ Wk,
                    const float* __restrict__ Wv)
{
    const int t = blockIdx.y;
    const float* src = (t==0) ? H : (t==1) ? Wq : (t==2) ? Wk : Wv;
    __half* dst = (t==0) ? g_Hh : g_Wh[t-1];
    const size_t n4 = ((t==0) ? (size_t)M_*HID_ : (size_t)HID_*HID_) / 4;
    size_t i = (size_t)blockIdx.x * 256 + threadIdx.x;
    if (i >= n4) return;
    float4 v = *(const float4*)(src + i*4);
    uint2 p = make_uint2(pack_h2(v.x, v.y), pack_h2(v.z, v.w));
    *(uint2*)(dst + i*4) = p;
}

// ================= QKV projection: fp16 mma GEMM (128x128 tiles) =================
#define BM 128
#define BN 128
#define BK 32
#define NKS (HID_/BK)          // 64
#define QASTR 40               // fp16 row stride (80 B)

__global__ __launch_bounds__(256)
void qkv_kernel(const float* __restrict__ bq,
                const float* __restrict__ bk,
                const float* __restrict__ bv)
{
    __shared__ __align__(16) __half sA[2][BM*QASTR];    // 10240 B each
    __shared__ __align__(16) __half sB[2][BN*QASTR];    // 10240 B each

    const int z  = blockIdx.z;
    const float* bias = (z==0) ? bq : (z==1) ? bk : bv;
    const __half* W_ = g_Wh[z];

    const int tid  = threadIdx.x;
    const int lane = tid & 31;
    const int wid  = tid >> 5;
    const int wm   = wid & 3;        // 4 warps along M (32 rows each)
    const int wn   = wid >> 2;       // 2 warps along N (64 cols each)
    const int m0   = blockIdx.y * BM;
    const int n0   = blockIdx.x * BN;

    const uint32_t aB[2] = { smem_u32(&sA[0][0]), smem_u32(&sA[1][0]) };
    const uint32_t bB[2] = { smem_u32(&sB[0][0]), smem_u32(&sB[1][0]) };

    float acc[2][8][4];
    #pragma unroll
    for (int i=0;i<2;i++)
        #pragma unroll
        for (int j=0;j<8;j++)
            #pragma unroll
            for (int e=0;e<4;e++) acc[i][j][e]=0.f;

    const int a_row = lane & 15;
    const int a_col = ((lane >> 4) & 1) * 8;
    const int b_key = (lane & 7) + ((lane >> 4) << 3);   // 16-row B group
    const int b_col = ((lane >> 3) & 1) * 8;

    auto load_stage = [&](int st, int k0) {
        #pragma unroll
        for (int it = 0; it < 2; it++) {          // A: 128 rows x 4 chunks of 16B
            int i = tid + it*256;
            int r = i >> 2, c = i & 3;
            cpasync16(aB[st] + r*80 + c*16, g_Hh + (size_t)(m0 + r)*HID_ + k0 + c*8);
        }
        #pragma unroll
        for (int it = 0; it < 2; it++) {          // B: 128 rows x 4 chunks
            int i = tid + it*256;
            int r = i >> 2, c = i & 3;
            cpasync16(bB[st] + r*80 + c*16, W_ + (size_t)(n0 + r)*HID_ + k0 + c*8);
        }
        cp_commit();
    };

    load_stage(0, 0);

    for (int ks = 0; ks < NKS; ks++) {
        const int cur = ks & 1;
        if (ks + 1 < NKS) {
            load_stage(cur ^ 1, (ks+1)*BK);
            cp_wait<1>();
        } else {
            cp_wait<0>();
        }
        __syncthreads();

        #pragma unroll
        for (int k16 = 0; k16 < BK; k16 += 16) {
            uint32_t a[2][4];
            #pragma unroll
            for (int mi=0; mi<2; mi++) {
                int row = wm*32 + mi*16 + a_row;
                ldmx4(a[mi][0],a[mi][1],a[mi][2],a[mi][3],
                      aB[cur] + (row*QASTR + k16 + a_col)*2);
            }
            #pragma unroll
            for (int nj2=0; nj2<4; nj2++) {       // 16-col groups
                int row = wn*64 + nj2*16 + b_key;
                uint32_t bb[4];
                ldmx4(bb[0],bb[1],bb[2],bb[3], bB[cur] + (row*QASTR + k16 + b_col)*2);
                #pragma unroll
                for (int mi=0; mi<2; mi++) {
                    mma_fp16(acc[mi][nj2*2],   a[mi], &bb[0]);
                    mma_fp16(acc[mi][nj2*2+1], a[mi], &bb[2]);
                }
            }
        }
        __syncthreads();
    }

    // ---- epilogue: bias + RoPE -> fp16 planes [b][h][s][d] ----
    const float qscale = 0.08838834764831845f * LOG2E;   // 1/sqrt(HD) * log2(e)
    __half* Out = (z==0) ? g_Qh : (z==1) ? g_Kh : g_Vh;
    #pragma unroll
    for (int mi=0; mi<2; mi++) {
        #pragma unroll
        for (int nj=0; nj<8; nj++) {
            const int n  = n0 + wn*64 + nj*8 + (lane&3)*2;
            const int hh = n >> 7;
            const int d  = n & 127;
            const float bx = __ldg(&bias[n]), by = __ldg(&bias[n+1]);
            #pragma unroll
            for (int hf=0; hf<2; hf++) {
                const int m  = m0 + wm*32 + mi*16 + (lane>>2) + hf*8;
                const int bb = m >> 11;
                const int s  = m & 2047;
                float x = acc[mi][nj][hf*2+0] + bx;
                float y = acc[mi][nj][hf*2+1] + by;
                if (z < 2 && d < ROT_) {
                    float2 sc = g_rope[s*(ROT_/2) + (d>>1)];
                    float nx = x*sc.y - y*sc.x;
                    float ny = y*sc.y + x*sc.x;
                    x = nx; y = ny;
                }
                if (z == 0) { x *= qscale; y *= qscale; }
                const size_t o = (((size_t)bb*NH_ + hh)*S_ + s)*(size_t)HD_ + d;
                *(uint32_t*)(Out + o) = pack_h2(x, y);
            }
        }
    }
}

// ================= causal flash attention (fp16, exp2 domain) =================
#define AQ  128
#define AK  64
#define KSTR 136     // fp16 row stride in halves (272 B)

#define AT_Q    (AQ*KSTR)
#define AT_P    (AK*KSTR)
#define STG_H   (2*AT_P)
#define OFF_S0  AT_Q
#define OFF_S1  (AT_Q + STG_H)
#define OFF_MS  (AT_Q + 2*STG_H)
#define AT_SMEM_BYTES (OFF_MS*2 + 2*64*4)

__global__ __launch_bounds__(256)
void attn_kernel(const float* __restrict__ amask, float* __restrict__ out)
{
    extern __shared__ __align__(16) char smraw[];
    __half* SM = (__half*)smraw;
    float*  msbase = (float*)(SM + OFF_MS);
    const uint32_t smb = smem_u32(SM);

    const int qt = (gridDim.x - 1) - blockIdx.x;   // heavy tiles first
    const int h  = blockIdx.y, b = blockIdx.z;
    const size_t hoff = ((size_t)b*NH_ + h)*S_*HD_;
    const __half* Qg = g_Qh + hoff;
    const __half* Kg = g_Kh + hoff;
    const __half* Vg = g_Vh + hoff;

    const int tid  = threadIdx.x;
    const int lane = tid & 31;
    const int w    = tid >> 5;
    const int qbase = qt*AQ + w*16;

    auto load_kv = [&](int kt, int st) {
        const uint32_t sb = smb + (st ? OFF_S1 : OFF_S0)*2;
        #pragma unroll
        for (int it = 0; it < 4; it++) {
            int idx = tid + it*256;
            int r = idx >> 4;
            int c = (idx & 15) * 8;
            const size_t so = (size_t)(kt*AK + r)*HD_ + c;
            cpasync16(sb + (r*KSTR + c)*2,          Kg + so);
            cpasync16(sb + AT_P*2 + (r*KSTR + c)*2, Vg + so);
        }
        if (tid < 16)
            cpasync16(smb + OFF_MS*2 + st*256 + tid*16,
                      amask + (size_t)b*S_ + kt*AK + tid*4);
    };

    // ---- prologue: Q + stage 0 ----
    #pragma unroll
    for (int it = 0; it < 8; it++) {
        int idx = tid + it*256;
        int r = idx >> 4;
        int c = (idx & 15) * 8;
        cpasync16(smb + (r*KSTR + c)*2, Qg + (size_t)(qt*AQ + r)*HD_ + c);
    }
    load_kv(0, 0);
    cp_commit();

    float o[16][4];
    #pragma unroll
    for (int nt=0; nt<16; nt++)
        #pragma unroll
        for (int e=0;e<4;e++) o[nt][e]=0.f;

    float m0 = -INFINITY, m1 = -INFINITY, l0 = 0.f, l1 = 0.f;

    const int qa_row = lane & 15;
    const int qa_col = (lane >> 4) * 8;
    const int kb_key = (lane & 7) + ((lane >> 4) << 3);
    const int kb_col = ((lane >> 3) & 1) * 8;
    const int vb_key = (lane & 7) + (((lane >> 3) & 1) << 3);
    const int vb_col = (lane >> 4) * 8;

    cp_wait<0>();
    __syncthreads();
    uint32_t qf[8][4];
    #pragma unroll
    for (int ks = 0; ks < 8; ks++)
        ldmx4(qf[ks][0],qf[ks][1],qf[ks][2],qf[ks][3],
              smb + ((w*16+qa_row)*KSTR + ks*16 + qa_col)*2);

    const int ktmax = 2*qt + 1;
    for (int kt = 0; kt <= ktmax; kt++) {
        const int cur = kt & 1;
        if (kt > 0) { cp_wait<0>(); __syncthreads(); }
        if (kt + 1 <= ktmax) { load_kv(kt+1, cur ^ 1); cp_commit(); }

        const uint32_t ksb = smb + (cur ? OFF_S1 : OFF_S0)*2;
        const float* ms = msbase + cur*64;

        // ---- S = Q K^T (log2 domain: Q pre-scaled by 1/sqrt(HD)*log2e) ----
        float s[8][4];
        #pragma unroll
        for (int nt=0; nt<8; nt++)
            #pragma unroll
            for (int e=0;e<4;e++) s[nt][e]=0.f;

        #pragma unroll
        for (int ks = 0; ks < 8; ks++) {
            const int d0 = ks*16;
            #pragma unroll
            for (int ntp = 0; ntp < 4; ntp++) {
                const int n0 = ntp*16;
                uint32_t bh[4];
                ldmx4(bh[0],bh[1],bh[2],bh[3], ksb + ((n0+kb_key)*KSTR + d0 + kb_col)*2);
                mma_fp16(s[ntp*2],   qf[ks], &bh[0]);
                mma_fp16(s[ntp*2+1], qf[ks], &bh[2]);
            }
        }

        // ---- mask: amask (log2-scaled) always; causal compare only on diagonal tiles ----
        if (kt >= 2*qt) {
            const int qi0 = qbase + (lane>>2);
            const int qi1 = qi0 + 8;
            #pragma unroll
            for (int nt=0; nt<8; nt++) {
                const int kc = kt*AK + nt*8 + (lane&3)*2;
                const float am0 = ms[nt*8 + (lane&3)*2]     * LOG2E;
                const float am1 = ms[nt*8 + (lane&3)*2 + 1] * LOG2E;
                s[nt][0] = ((kc   <= qi0) ? s[nt][0] : -14427.f) + am0;
                s[nt][1] = ((kc+1 <= qi0) ? s[nt][1] : -14427.f) + am1;
                s[nt][2] = ((kc   <= qi1) ? s[nt][2] : -14427.f) + am0;
                s[nt][3] = ((kc+1 <= qi1) ? s[nt][3] : -14427.f) + am1;
            }
        } else {
            #pragma unroll
            for (int nt=0; nt<8; nt++) {
                const float am0 = ms[nt*8 + (lane&3)*2]     * LOG2E;
                const float am1 = ms[nt*8 + (lane&3)*2 + 1] * LOG2E;
                s[nt][0] += am0; s[nt][1] += am1;
                s[nt][2] += am0; s[nt][3] += am1;
            }
        }

        // ---- online softmax (base-2) ----
        float mx0 = -INFINITY, mx1 = -INFINITY;
        #pragma unroll
        for (int nt=0; nt<8; nt++) {
            mx0 = fmaxf(mx0, fmaxf(s[nt][0], s[nt][1]));
            mx1 = fmaxf(mx1, fmaxf(s[nt][2], s[nt][3]));
        }
        mx0 = fmaxf(mx0, __shfl_xor_sync(0xffffffffu, mx0, 1));
        mx0 = fmaxf(mx0, __shfl_xor_sync(0xffffffffu, mx0, 2));
        mx1 = fmaxf(mx1, __shfl_xor_sync(0xffffffffu, mx1, 1));
        mx1 = fmaxf(mx1, __shfl_xor_sync(0xffffffffu, mx1, 2));
        const float mn0 = fmaxf(m0, mx0), mn1 = fmaxf(m1, mx1);
        const float al0 = exp2f(m0 - mn0), al1 = exp2f(m1 - mn1);
        m0 = mn0; m1 = mn1;

        float sum0 = 0.f, sum1 = 0.f;
        #pragma unroll
        for (int nt=0; nt<8; nt++) {
            s[nt][0] = exp2f(s[nt][0] - mn0);
            s[nt][1] = exp2f(s[nt][1] - mn0);
            s[nt][2] = exp2f(s[nt][2] - mn1);
            s[nt][3] = exp2f(s[nt][3] - mn1);
            sum0 += s[nt][0] + s[nt][1];
            sum1 += s[nt][2] + s[nt][3];
        }
        sum0 += __shfl_xor_sync(0xffffffffu, sum0, 1);
        sum0 += __shfl_xor_sync(0xffffffffu, sum0, 2);
        sum1 += __shfl_xor_sync(0xffffffffu, sum1, 1);
        sum1 += __shfl_xor_sync(0xffffffffu, sum1, 2);
        l0 = l0*al0 + sum0;
        l1 = l1*al1 + sum1;

        #pragma unroll
        for (int nt=0; nt<16; nt++) {
            o[nt][0] *= al0; o[nt][1] *= al0;
            o[nt][2] *= al1; o[nt][3] *= al1;
        }

        // ---- O += P V ----
        #pragma unroll
        for (int ks = 0; ks < 4; ks++) {
            const int t0 = 2*ks, t1 = 2*ks+1;
            uint32_t pa[4];
            pa[0] = pack_h2(s[t0][0], s[t0][1]);
            pa[1] = pack_h2(s[t0][2], s[t0][3]);
            pa[2] = pack_h2(s[t1][0], s[t1][1]);
            pa[3] = pack_h2(s[t1][2], s[t1][3]);
            const int k0 = ks*16;
            #pragma unroll
            for (int ntp = 0; ntp < 8; ntp++) {
                const int n0 = ntp*16;
                uint32_t vh[4];
                ldmx4t(vh[0],vh[1],vh[2],vh[3],
                       ksb + AT_P*2 + ((k0+vb_key)*KSTR + n0 + vb_col)*2);
                mma_fp16(o[ntp*2],   pa, &vh[0]);
                mma_fp16(o[ntp*2+1], pa, &vh[2]);
            }
        }
    }

    // ---- normalize + write ----
    const float inv0 = 1.0f / l0;
    const float inv1 = 1.0f / l1;
    const int r0 = qbase + (lane>>2);
    const int r1 = r0 + 8;
    #pragma unroll
    for (int nt=0; nt<16; nt++) {
        const int col = h*HD_ + nt*8 + (lane&3)*2;
        float2 w0 = make_float2(o[nt][0]*inv0, o[nt][1]*inv0);
        float2 w1 = make_float2(o[nt][2]*inv1, o[nt][3]*inv1);
        *(float2*)&out[(size_t)(b*S_ + r0)*HID_ + col] = w0;
        *(float2*)&out[(size_t)(b*S_ + r1)*HID_ + col] = w1;
    }
}

// ================= launch =================
extern "C" void kernel_launch(void* const* d_in, const int* in_sizes, int n_in,
                              void* d_out, int out_size)
{
    const float* H  = (const float*)d_in[0];
    const float* am = (const float*)d_in[1];
    const float* Wq = (const float*)d_in[2];
    const float* bq = (const float*)d_in[3];
    const float* Wk = (const float*)d_in[4];
    const float* bk = (const float*)d_in[5];
    const float* Wv = (const float*)d_in[6];
    const float* bv = (const float*)d_in[7];
    float* out = (float*)d_out;

    cudaFuncSetAttribute(attn_kernel,
                         cudaFuncAttributeMaxDynamicSharedMemorySize, AT_SMEM_BYTES);

    rope_init_kernel<<<(S_*ROT_/2 + 255)/256, 256>>>();

    {   // fp32 -> fp16 planes
        dim3 cgrid((unsigned)(((size_t)M_*HID_/4 + 255)/256), 4);
        convert_kernel<<<cgrid, 256>>>(H, Wq, Wk, Wv);
    }

    dim3 ggrid(HID_/BN, M_/BM, 3);        // 16 x 32 x 3
    qkv_kernel<<<ggrid, 256>>>(bq, bk, bv);

    dim3 agrid(S_/AQ, NH_, B_);           // 16 x 16 x 2
    attn_kernel<<<agrid, 256, AT_SMEM_BYTES>>>(am, out);
}